// round 1
// baseline (speedup 1.0000x reference)
#include <cuda_runtime.h>
#include <math.h>

// Problem constants (fixed by the dataset)
#define TSEQ   2048
#define DDIM   4096
#define NQ     32
#define NKV    8
#define HD     128
#define NSLOTS 32768
#define QKVC   6144   // 32*128 + 8*128 + 8*128

// ---------------- scratch (static device allocations; no cudaMalloc) -------
__device__ float g_QKV[(size_t)TSEQ * QKVC];       // [t][6144]
__device__ float g_Q  [(size_t)NQ  * TSEQ * HD];   // [n][t][h] (roped, scaled)
__device__ float g_K  [(size_t)NKV * TSEQ * HD];   // [kh][t][h] (roped)
__device__ float g_V  [(size_t)NKV * TSEQ * HD];   // [kh][t][h]
__device__ float g_A2 [(size_t)TSEQ * DDIM];       // [t][n*128+h]

// ---------------- generic 128x128 fp32 GEMM tile ---------------------------
// C[row, col] tile at (rowBase, 0-of-C-pointer). A row-major [.., lda],
// B row-major [Kdim, ldb], C row-major [.., ldc]. 256 threads.
__device__ __forceinline__ void gemm_tile128(
    const float* __restrict__ A, int lda,
    const float* __restrict__ B, int ldb,
    float* __restrict__ C, int ldc,
    int Kdim, int rowBase)
{
    constexpr int BM = 128, BN = 128, BK = 16, TM = 8, TN = 8;
    __shared__ float As[BK][BM];   // transposed
    __shared__ float Bs[BK][BN];

    const int tid  = threadIdx.x;
    const int aRow = tid >> 2;            // 0..63
    const int aCol = (tid & 3) << 2;      // 0,4,8,12
    const int bRow = tid >> 5;            // 0..7
    const int bCol = (tid & 31) << 2;     // 0..124
    const int tRow = (tid >> 4) << 3;     // 0..120 step 8
    const int tCol = (tid & 15) << 3;

    const float* Ab = A + (size_t)rowBase * lda;
    float acc[TM][TN];
#pragma unroll
    for (int i = 0; i < TM; i++)
#pragma unroll
        for (int j = 0; j < TN; j++) acc[i][j] = 0.f;

    for (int k0 = 0; k0 < Kdim; k0 += BK) {
#pragma unroll
        for (int r = 0; r < 2; r++) {
            int row = aRow + r * 64;
            float4 v = *(const float4*)(Ab + (size_t)row * lda + k0 + aCol);
            As[aCol + 0][row] = v.x;
            As[aCol + 1][row] = v.y;
            As[aCol + 2][row] = v.z;
            As[aCol + 3][row] = v.w;
        }
#pragma unroll
        for (int r = 0; r < 2; r++) {
            int row = bRow + r * 8;
            *(float4*)(&Bs[row][bCol]) =
                *(const float4*)(B + (size_t)(k0 + row) * ldb + bCol);
        }
        __syncthreads();
#pragma unroll
        for (int k = 0; k < BK; k++) {
            float regM[TM], regN[TN];
            *(float4*)&regM[0] = *(const float4*)&As[k][tRow];
            *(float4*)&regM[4] = *(const float4*)&As[k][tRow + 4];
            *(float4*)&regN[0] = *(const float4*)&Bs[k][tCol];
            *(float4*)&regN[4] = *(const float4*)&Bs[k][tCol + 4];
#pragma unroll
            for (int i = 0; i < TM; i++)
#pragma unroll
                for (int j = 0; j < TN; j++)
                    acc[i][j] += regM[i] * regN[j];
        }
        __syncthreads();
    }
#pragma unroll
    for (int i = 0; i < TM; i++) {
        float* crow = C + (size_t)(rowBase + tRow + i) * ldc + tCol;
        float4 v0 = {acc[i][0], acc[i][1], acc[i][2], acc[i][3]};
        float4 v1 = {acc[i][4], acc[i][5], acc[i][6], acc[i][7]};
        *(float4*)(crow)     = v0;
        *(float4*)(crow + 4) = v1;
    }
}

// ---------------- kernel 1: fused QKV projection ---------------------------
// grid.x = 48 column blocks (32 q heads, 8 k heads, 8 v heads), grid.y = T/128
__global__ __launch_bounds__(256) void k_gemm_qkv(
    const float* __restrict__ x,
    const float* __restrict__ wq,
    const float* __restrict__ wk,
    const float* __restrict__ wv)
{
    int cb = blockIdx.x;
    const float* B;
    if (cb < 32)      B = wq + (size_t)cb * DDIM * HD;
    else if (cb < 40) B = wk + (size_t)(cb - 32) * DDIM * HD;
    else              B = wv + (size_t)(cb - 40) * DDIM * HD;
    gemm_tile128(x, DDIM, B, HD, g_QKV + (size_t)cb * HD, QKVC,
                 DDIM, blockIdx.y * 128);
}

// ---------------- kernel 2: RoPE + layout split + cache writeback ----------
__global__ __launch_bounds__(256) void k_rope(
    const int* __restrict__ positions,
    const int* __restrict__ widx,
    float* __restrict__ out_kc,
    float* __restrict__ out_vc)
{
    const int t = blockIdx.x;
    __shared__ float cs[64], sn[64];
    const int pos = positions[t];
    if (threadIdx.x < 64) {
        int i = threadIdx.x;
        double e = -((double)(2 * i) / 128.0);
        float inv = (float)pow(500000.0, e);
        float ang = (float)pos * inv;
        float s, c;
        sincosf(ang, &s, &c);
        cs[i] = c;
        sn[i] = s;
    }
    __syncthreads();

    const float* row = g_QKV + (size_t)t * QKVC;
    const int wi = widx[t];
    const float qscale = 0.08838834764831845f;  // 128^-0.5

    // q heads: 32 * 64 rotation pairs
    for (int idx = threadIdx.x; idx < NQ * 64; idx += blockDim.x) {
        int n = idx >> 6, i = idx & 63;
        float x1 = row[n * HD + i];
        float x2 = row[n * HD + 64 + i];
        float c = cs[i], s = sn[i];
        float* qd = g_Q + ((size_t)n * TSEQ + t) * HD;
        qd[i]      = (x1 * c - x2 * s) * qscale;
        qd[64 + i] = (x2 * c + x1 * s) * qscale;
    }
    // k heads: 8 * 64 pairs (+ cache writeback)
    for (int idx = threadIdx.x; idx < NKV * 64; idx += blockDim.x) {
        int kh = idx >> 6, i = idx & 63;
        float x1 = row[NQ * HD + kh * HD + i];
        float x2 = row[NQ * HD + kh * HD + 64 + i];
        float c = cs[i], s = sn[i];
        float o1 = x1 * c - x2 * s;
        float o2 = x2 * c + x1 * s;
        float* kd = g_K + ((size_t)kh * TSEQ + t) * HD;
        kd[i] = o1; kd[64 + i] = o2;
        float* kc = out_kc + ((size_t)wi * NKV + kh) * HD;
        kc[i] = o1; kc[64 + i] = o2;
    }
    // v: plain copy (+ cache writeback)
    for (int idx = threadIdx.x; idx < NKV * HD; idx += blockDim.x) {
        int kh = idx >> 7, h = idx & 127;
        float v = row[(NQ + NKV) * HD + kh * HD + h];
        g_V[((size_t)kh * TSEQ + t) * HD + h] = v;
        out_vc[((size_t)wi * NKV + kh) * HD + h] = v;
    }
}

// ---------------- kernel 3: causal flash attention -------------------------
// grid = (T/64, NQ), 256 threads (8 warps). Each warp owns 8 query rows.
// Key chunk = 32 (one key per lane). acc distributed 4 dims per lane.
#define ATTN_SMEM_FLOATS (64 * 128 + 128 * 33 + 32 * 132 + 32)
__global__ __launch_bounds__(256) void k_attn(const int* __restrict__ positions)
{
    extern __shared__ float sm[];
    float* Qs = sm;                       // [64][128]
    float* Kt = Qs + 64 * 128;            // [128][33] transposed, padded
    float* Vs = Kt + 128 * 33;            // [32][132] padded (16B-aligned rows)
    int*   Ps = (int*)(Vs + 32 * 132);    // [32]

    const int n    = blockIdx.y;
    const int kh   = n >> 2;
    const int t0   = blockIdx.x * 64;
    const int tid  = threadIdx.x;
    const int lane = tid & 31;
    const int warp = tid >> 5;

    // load Q tile
    const float* Qg = g_Q + ((size_t)n * TSEQ + t0) * HD;
    for (int i = tid * 4; i < 64 * 128; i += 256 * 4)
        *(float4*)(Qs + i) = *(const float4*)(Qg + i);

    const int rbase = t0 + warp * 8;
    int pt[8];
#pragma unroll
    for (int r = 0; r < 8; r++) pt[r] = positions[rbase + r];

    float m[8], l[8], acc[8][4];
#pragma unroll
    for (int r = 0; r < 8; r++) {
        m[r] = -1e30f; l[r] = 0.f;
        acc[r][0] = acc[r][1] = acc[r][2] = acc[r][3] = 0.f;
    }

    const float* Kg = g_K + (size_t)kh * TSEQ * HD;
    const float* Vg = g_V + (size_t)kh * TSEQ * HD;

    const int nchunks = (t0 + 64) / 32;
    const int jj = tid >> 3;              // 0..31 key index for loads
    const int hb = (tid & 7) * 16;        // 16 h-dims per thread

    for (int ch = 0; ch < nchunks; ch++) {
        const int s0 = ch * 32;
        __syncthreads();
        {
            const float* kr = Kg + (size_t)(s0 + jj) * HD + hb;
#pragma unroll
            for (int u = 0; u < 16; u += 4) {
                float4 v = *(const float4*)(kr + u);
                Kt[(hb + u + 0) * 33 + jj] = v.x;
                Kt[(hb + u + 1) * 33 + jj] = v.y;
                Kt[(hb + u + 2) * 33 + jj] = v.z;
                Kt[(hb + u + 3) * 33 + jj] = v.w;
            }
            const float* vr = Vg + (size_t)(s0 + jj) * HD + hb;
#pragma unroll
            for (int u = 0; u < 16; u += 4)
                *(float4*)(&Vs[jj * 132 + hb + u]) = *(const float4*)(vr + u);
        }
        if (tid < 32) Ps[tid] = positions[s0 + tid];
        __syncthreads();

        // scores: lane owns key s0+lane
        float sc[8];
#pragma unroll
        for (int r = 0; r < 8; r++) sc[r] = 0.f;
#pragma unroll 4
        for (int h = 0; h < 128; h++) {
            float kv = Kt[h * 33 + lane];
#pragma unroll
            for (int r = 0; r < 8; r++)
                sc[r] += Qs[(warp * 8 + r) * 128 + h] * kv;
        }

        const int ps = Ps[lane];
        float p[8];
#pragma unroll
        for (int r = 0; r < 8; r++) {
            float s = (pt[r] >= ps) ? sc[r] : -1e30f;
            float mx = s;
#pragma unroll
            for (int off = 16; off > 0; off >>= 1)
                mx = fmaxf(mx, __shfl_xor_sync(0xffffffffu, mx, off));
            float mn   = fmaxf(m[r], mx);
            float corr = __expf(m[r] - mn);
            float pv   = __expf(s - mn);
            float sum  = pv;
#pragma unroll
            for (int off = 16; off > 0; off >>= 1)
                sum += __shfl_xor_sync(0xffffffffu, sum, off);
            l[r] = l[r] * corr + sum;
            m[r] = mn;
            acc[r][0] *= corr; acc[r][1] *= corr;
            acc[r][2] *= corr; acc[r][3] *= corr;
            p[r] = pv;
        }

        // acc += P @ V  (lane owns h dims lane*4..+3)
#pragma unroll
        for (int j = 0; j < 32; j++) {
            float4 v = *(const float4*)(&Vs[j * 132 + lane * 4]);
#pragma unroll
            for (int r = 0; r < 8; r++) {
                float pj = __shfl_sync(0xffffffffu, p[r], j);
                acc[r][0] += pj * v.x;
                acc[r][1] += pj * v.y;
                acc[r][2] += pj * v.z;
                acc[r][3] += pj * v.w;
            }
        }
    }

#pragma unroll
    for (int r = 0; r < 8; r++) {
        float inv = 1.f / l[r];
        float4 o = {acc[r][0] * inv, acc[r][1] * inv,
                    acc[r][2] * inv, acc[r][3] * inv};
        *(float4*)(g_A2 + (size_t)(rbase + r) * DDIM + n * HD + lane * 4) = o;
    }
}

// ---------------- kernel 4: output projection ------------------------------
__global__ __launch_bounds__(256) void k_gemm_o(
    const float* __restrict__ wo, float* __restrict__ out_o)
{
    // A2 [T, 4096] @ wo [4096 (= n*128+h), 4096] -> o [T, 4096]
    gemm_tile128(g_A2, DDIM, wo + (size_t)blockIdx.x * 128, DDIM,
                 out_o + (size_t)blockIdx.x * 128, DDIM,
                 DDIM, blockIdx.y * 128);
}

// ---------------- launch ----------------------------------------------------
extern "C" void kernel_launch(void* const* d_in, const int* in_sizes, int n_in,
                              void* d_out, int out_size)
{
    (void)in_sizes; (void)n_in; (void)out_size;
    const float* x     = (const float*)d_in[0];
    const float* wq    = (const float*)d_in[1];
    const float* wk    = (const float*)d_in[2];
    const float* wv    = (const float*)d_in[3];
    const float* wo    = (const float*)d_in[4];
    const float* kc_in = (const float*)d_in[5];
    const float* vc_in = (const float*)d_in[6];
    const int* positions = (const int*)d_in[7];
    const int* widx      = (const int*)d_in[8];

    float* out_kc = (float*)d_out;
    float* out_vc = out_kc + (size_t)NSLOTS * NKV * HD;
    float* out_o  = out_vc + (size_t)NSLOTS * NKV * HD;

    const size_t cacheBytes = (size_t)NSLOTS * NKV * HD * sizeof(float);
    cudaMemcpyAsync(out_kc, kc_in, cacheBytes, cudaMemcpyDeviceToDevice, 0);
    cudaMemcpyAsync(out_vc, vc_in, cacheBytes, cudaMemcpyDeviceToDevice, 0);

    k_gemm_qkv<<<dim3(48, TSEQ / 128), 256, 0, 0>>>(x, wq, wk, wv);
    k_rope<<<TSEQ, 256, 0, 0>>>(positions, widx, out_kc, out_vc);

    const int attn_smem = ATTN_SMEM_FLOATS * (int)sizeof(float);
    cudaFuncSetAttribute(k_attn, cudaFuncAttributeMaxDynamicSharedMemorySize,
                         attn_smem);
    k_attn<<<dim3(TSEQ / 64, NQ), 256, attn_smem, 0>>>(positions);

    k_gemm_o<<<dim3(DDIM / 128, TSEQ / 128), 256, 0, 0>>>(wo, out_o);
}

// round 3
// speedup vs baseline: 3.1520x; 3.1520x over previous
#include <cuda_runtime.h>
#include <cstdint>
#include <stdint.h>
#include <math.h>

// Problem constants (fixed by the dataset)
#define TSEQ   2048
#define DDIM   4096
#define NQ     32
#define NKV    8
#define HD     128
#define NSLOTS 32768
#define QKVC   6144   // 32*128 + 8*128 + 8*128

// ---------------- scratch (static device allocations; no cudaMalloc) -------
__device__ float g_QKV[(size_t)TSEQ * QKVC];       // [t][6144]
__device__ float g_Q  [(size_t)NQ  * TSEQ * HD];   // [n][t][h] (roped, scaled)
__device__ float g_K  [(size_t)NKV * TSEQ * HD];   // [kh][t][h] (roped)
__device__ float g_V  [(size_t)NKV * TSEQ * HD];   // [kh][t][h]
__device__ float g_A2 [(size_t)TSEQ * DDIM];       // [t][n*128+h]

// ---------------- tf32 mma helpers -----------------------------------------
__device__ __forceinline__ unsigned f2tf(float x) {
    unsigned r;
    asm("cvt.rna.tf32.f32 %0, %1;" : "=r"(r) : "f"(x));
    return r;
}

__device__ __forceinline__ void mma_tf32(float* d, const unsigned* a,
                                         const unsigned* b) {
    asm volatile(
        "mma.sync.aligned.m16n8k8.row.col.f32.tf32.tf32.f32 "
        "{%0,%1,%2,%3}, {%4,%5,%6,%7}, {%8,%9}, {%0,%1,%2,%3};"
        : "+f"(d[0]), "+f"(d[1]), "+f"(d[2]), "+f"(d[3])
        : "r"(a[0]), "r"(a[1]), "r"(a[2]), "r"(a[3]), "r"(b[0]), "r"(b[1]));
}

__device__ __forceinline__ void cp16(unsigned smem, const float* g) {
    asm volatile("cp.async.cg.shared.global [%0], [%1], 16;\n"
                 :: "r"(smem), "l"(g));
}

// ---------------- 128x128 tf32 tensor-core GEMM tile -----------------------
// C[rowBase..+128, 0..128 of C pointer] = A[rowBase.., :] * B[:, 0..128]
// A row-major [.., lda]; B row-major [Kdim, ldb]; 256 threads (8 warps 2x4).
// Kdim must be a multiple of 16.
__device__ __forceinline__ void gemm_mma128(
    const float* __restrict__ A, int lda,
    const float* __restrict__ B, int ldb,
    float* __restrict__ C, int ldc,
    int Kdim, int rowBase)
{
    __shared__ float As[2][128][20];   // pad 20: conflict-free (g,t) frag loads
    __shared__ float Bs[2][16][136];   // pad 136: conflict-free (t,g) frag loads

    const int tid  = threadIdx.x;
    const int lane = tid & 31;
    const int warp = tid >> 5;
    const int wM   = warp >> 2;        // 0..1 -> 64-row slab
    const int wN   = warp & 3;         // 0..3 -> 32-col slab
    const int g    = lane >> 2;        // groupID 0..7
    const int t    = lane & 3;         // threadID-in-group 0..3

    const int ar = tid >> 2, ac = (tid & 3) << 2;   // A ld: 64 rows x 4 f4
    const int br = tid >> 5, bc = (tid & 31) << 2;  // B ld: 8 rows x 32 f4

    const float* Ab = A + (size_t)rowBase * lda;

    float acc[4][4][4];
#pragma unroll
    for (int mt = 0; mt < 4; mt++)
#pragma unroll
        for (int nt = 0; nt < 4; nt++)
#pragma unroll
            for (int i = 0; i < 4; i++) acc[mt][nt][i] = 0.f;

    const unsigned sA0 = (unsigned)__cvta_generic_to_shared(&As[0][0][0]);
    const unsigned sB0 = (unsigned)__cvta_generic_to_shared(&Bs[0][0][0]);

    // ---- prologue: stage 0 ----
    {
        cp16(sA0 + (unsigned)((ar)      * 20 + ac) * 4u, Ab + (size_t)ar * lda + ac);
        cp16(sA0 + (unsigned)((ar + 64) * 20 + ac) * 4u, Ab + (size_t)(ar + 64) * lda + ac);
        cp16(sB0 + (unsigned)((br)      * 136 + bc) * 4u, B + (size_t)br * ldb + bc);
        cp16(sB0 + (unsigned)((br + 8)  * 136 + bc) * 4u, B + (size_t)(br + 8) * ldb + bc);
        asm volatile("cp.async.commit_group;");
    }

    const int niter = Kdim >> 4;
    for (int it = 0; it < niter; it++) {
        if (it + 1 < niter) {
            const int k0 = (it + 1) << 4;
            const unsigned stA = sA0 + (unsigned)((it + 1) & 1) * (unsigned)(128 * 20 * 4);
            const unsigned stB = sB0 + (unsigned)((it + 1) & 1) * (unsigned)(16 * 136 * 4);
            cp16(stA + (unsigned)((ar)      * 20 + ac) * 4u, Ab + (size_t)ar * lda + k0 + ac);
            cp16(stA + (unsigned)((ar + 64) * 20 + ac) * 4u, Ab + (size_t)(ar + 64) * lda + k0 + ac);
            cp16(stB + (unsigned)((br)      * 136 + bc) * 4u, B + (size_t)(k0 + br) * ldb + bc);
            cp16(stB + (unsigned)((br + 8)  * 136 + bc) * 4u, B + (size_t)(k0 + br + 8) * ldb + bc);
        }
        asm volatile("cp.async.commit_group;");
        asm volatile("cp.async.wait_group 1;");
        __syncthreads();

        const int st = it & 1;
#pragma unroll
        for (int ks = 0; ks < 2; ks++) {
            unsigned af[4][4], bf[4][2];
#pragma unroll
            for (int mt = 0; mt < 4; mt++) {
                const float* p = &As[st][wM * 64 + mt * 16 + g][ks * 8 + t];
                af[mt][0] = f2tf(p[0]);
                af[mt][1] = f2tf(p[8 * 20]);
                af[mt][2] = f2tf(p[4]);
                af[mt][3] = f2tf(p[8 * 20 + 4]);
            }
#pragma unroll
            for (int nt = 0; nt < 4; nt++) {
                bf[nt][0] = f2tf(Bs[st][ks * 8 + t    ][wN * 32 + nt * 8 + g]);
                bf[nt][1] = f2tf(Bs[st][ks * 8 + t + 4][wN * 32 + nt * 8 + g]);
            }
#pragma unroll
            for (int mt = 0; mt < 4; mt++)
#pragma unroll
                for (int nt = 0; nt < 4; nt++)
                    mma_tf32(acc[mt][nt], af[mt], bf[nt]);
        }
        __syncthreads();
    }

    // ---- epilogue ----
#pragma unroll
    for (int mt = 0; mt < 4; mt++) {
#pragma unroll
        for (int nt = 0; nt < 4; nt++) {
            const int r0 = rowBase + wM * 64 + mt * 16 + g;
            const int c0 = wN * 32 + nt * 8 + 2 * t;
            float2 v0 = {acc[mt][nt][0], acc[mt][nt][1]};
            float2 v1 = {acc[mt][nt][2], acc[mt][nt][3]};
            *(float2*)(C + (size_t)r0 * ldc + c0)       = v0;
            *(float2*)(C + (size_t)(r0 + 8) * ldc + c0) = v1;
        }
    }
}

// ---------------- kernel 1: fused QKV projection ---------------------------
__global__ __launch_bounds__(256) void k_gemm_qkv(
    const float* __restrict__ x,
    const float* __restrict__ wq,
    const float* __restrict__ wk,
    const float* __restrict__ wv)
{
    int cb = blockIdx.x;
    const float* B;
    if (cb < 32)      B = wq + (size_t)cb * DDIM * HD;
    else if (cb < 40) B = wk + (size_t)(cb - 32) * DDIM * HD;
    else              B = wv + (size_t)(cb - 40) * DDIM * HD;
    gemm_mma128(x, DDIM, B, HD, g_QKV + (size_t)cb * HD, QKVC,
                DDIM, blockIdx.y * 128);
}

// ---------------- kernel 2: RoPE + layout split + cache writeback ----------
__global__ __launch_bounds__(256) void k_rope(
    const int* __restrict__ positions,
    const int* __restrict__ widx,
    float* __restrict__ out_kc,
    float* __restrict__ out_vc)
{
    const int t = blockIdx.x;
    __shared__ float cs[64], sn[64];
    const int pos = positions[t];
    if (threadIdx.x < 64) {
        int i = threadIdx.x;
        double e = -((double)(2 * i) / 128.0);
        float inv = (float)pow(500000.0, e);
        float ang = (float)pos * inv;
        float s, c;
        sincosf(ang, &s, &c);
        cs[i] = c;
        sn[i] = s;
    }
    __syncthreads();

    const float* row = g_QKV + (size_t)t * QKVC;
    const int wi = widx[t];
    const float qscale = 0.08838834764831845f;  // 128^-0.5

    for (int idx = threadIdx.x; idx < NQ * 64; idx += blockDim.x) {
        int n = idx >> 6, i = idx & 63;
        float x1 = row[n * HD + i];
        float x2 = row[n * HD + 64 + i];
        float c = cs[i], s = sn[i];
        float* qd = g_Q + ((size_t)n * TSEQ + t) * HD;
        qd[i]      = (x1 * c - x2 * s) * qscale;
        qd[64 + i] = (x2 * c + x1 * s) * qscale;
    }
    for (int idx = threadIdx.x; idx < NKV * 64; idx += blockDim.x) {
        int kh = idx >> 6, i = idx & 63;
        float x1 = row[NQ * HD + kh * HD + i];
        float x2 = row[NQ * HD + kh * HD + 64 + i];
        float c = cs[i], s = sn[i];
        float o1 = x1 * c - x2 * s;
        float o2 = x2 * c + x1 * s;
        float* kd = g_K + ((size_t)kh * TSEQ + t) * HD;
        kd[i] = o1; kd[64 + i] = o2;
        float* kc = out_kc + ((size_t)wi * NKV + kh) * HD;
        kc[i] = o1; kc[64 + i] = o2;
    }
    for (int idx = threadIdx.x; idx < NKV * HD; idx += blockDim.x) {
        int kh = idx >> 7, h = idx & 127;
        float v = row[(NQ + NKV) * HD + kh * HD + h];
        g_V[((size_t)kh * TSEQ + t) * HD + h] = v;
        out_vc[((size_t)wi * NKV + kh) * HD + h] = v;
    }
}

// ---------------- kernel 3: causal flash attention (unchanged) -------------
#define ATTN_SMEM_FLOATS (64 * 128 + 128 * 33 + 32 * 132 + 32)
__global__ __launch_bounds__(256) void k_attn(const int* __restrict__ positions)
{
    extern __shared__ float sm[];
    float* Qs = sm;                       // [64][128]
    float* Kt = Qs + 64 * 128;            // [128][33]
    float* Vs = Kt + 128 * 33;            // [32][132]
    int*   Ps = (int*)(Vs + 32 * 132);    // [32]

    const int n    = blockIdx.y;
    const int kh   = n >> 2;
    const int t0   = blockIdx.x * 64;
    const int tid  = threadIdx.x;
    const int lane = tid & 31;
    const int warp = tid >> 5;

    const float* Qg = g_Q + ((size_t)n * TSEQ + t0) * HD;
    for (int i = tid * 4; i < 64 * 128; i += 256 * 4)
        *(float4*)(Qs + i) = *(const float4*)(Qg + i);

    const int rbase = t0 + warp * 8;
    int pt[8];
#pragma unroll
    for (int r = 0; r < 8; r++) pt[r] = positions[rbase + r];

    float m[8], l[8], acc[8][4];
#pragma unroll
    for (int r = 0; r < 8; r++) {
        m[r] = -1e30f; l[r] = 0.f;
        acc[r][0] = acc[r][1] = acc[r][2] = acc[r][3] = 0.f;
    }

    const float* Kg = g_K + (size_t)kh * TSEQ * HD;
    const float* Vg = g_V + (size_t)kh * TSEQ * HD;

    const int nchunks = (t0 + 64) / 32;
    const int jj = tid >> 3;
    const int hb = (tid & 7) * 16;

    for (int ch = 0; ch < nchunks; ch++) {
        const int s0 = ch * 32;
        __syncthreads();
        {
            const float* kr = Kg + (size_t)(s0 + jj) * HD + hb;
#pragma unroll
            for (int u = 0; u < 16; u += 4) {
                float4 v = *(const float4*)(kr + u);
                Kt[(hb + u + 0) * 33 + jj] = v.x;
                Kt[(hb + u + 1) * 33 + jj] = v.y;
                Kt[(hb + u + 2) * 33 + jj] = v.z;
                Kt[(hb + u + 3) * 33 + jj] = v.w;
            }
            const float* vr = Vg + (size_t)(s0 + jj) * HD + hb;
#pragma unroll
            for (int u = 0; u < 16; u += 4)
                *(float4*)(&Vs[jj * 132 + hb + u]) = *(const float4*)(vr + u);
        }
        if (tid < 32) Ps[tid] = positions[s0 + tid];
        __syncthreads();

        float sc[8];
#pragma unroll
        for (int r = 0; r < 8; r++) sc[r] = 0.f;
#pragma unroll 4
        for (int h = 0; h < 128; h++) {
            float kv = Kt[h * 33 + lane];
#pragma unroll
            for (int r = 0; r < 8; r++)
                sc[r] += Qs[(warp * 8 + r) * 128 + h] * kv;
        }

        const int ps = Ps[lane];
        float p[8];
#pragma unroll
        for (int r = 0; r < 8; r++) {
            float s = (pt[r] >= ps) ? sc[r] : -1e30f;
            float mx = s;
#pragma unroll
            for (int off = 16; off > 0; off >>= 1)
                mx = fmaxf(mx, __shfl_xor_sync(0xffffffffu, mx, off));
            float mn   = fmaxf(m[r], mx);
            float corr = __expf(m[r] - mn);
            float pv   = __expf(s - mn);
            float sum  = pv;
#pragma unroll
            for (int off = 16; off > 0; off >>= 1)
                sum += __shfl_xor_sync(0xffffffffu, sum, off);
            l[r] = l[r] * corr + sum;
            m[r] = mn;
            acc[r][0] *= corr; acc[r][1] *= corr;
            acc[r][2] *= corr; acc[r][3] *= corr;
            p[r] = pv;
        }

#pragma unroll
        for (int j = 0; j < 32; j++) {
            float4 v = *(const float4*)(&Vs[j * 132 + lane * 4]);
#pragma unroll
            for (int r = 0; r < 8; r++) {
                float pj = __shfl_sync(0xffffffffu, p[r], j);
                acc[r][0] += pj * v.x;
                acc[r][1] += pj * v.y;
                acc[r][2] += pj * v.z;
                acc[r][3] += pj * v.w;
            }
        }
    }

#pragma unroll
    for (int r = 0; r < 8; r++) {
        float inv = 1.f / l[r];
        float4 o = {acc[r][0] * inv, acc[r][1] * inv,
                    acc[r][2] * inv, acc[r][3] * inv};
        *(float4*)(g_A2 + (size_t)(rbase + r) * DDIM + n * HD + lane * 4) = o;
    }
}

// ---------------- kernel 4: output projection ------------------------------
__global__ __launch_bounds__(256) void k_gemm_o(
    const float* __restrict__ wo, float* __restrict__ out_o)
{
    gemm_mma128(g_A2, DDIM, wo + (size_t)blockIdx.x * 128, DDIM,
                out_o + (size_t)blockIdx.x * 128, DDIM,
                DDIM, blockIdx.y * 128);
}

// ---------------- launch ----------------------------------------------------
extern "C" void kernel_launch(void* const* d_in, const int* in_sizes, int n_in,
                              void* d_out, int out_size)
{
    (void)in_sizes; (void)n_in; (void)out_size;
    const float* x     = (const float*)d_in[0];
    const float* wq    = (const float*)d_in[1];
    const float* wk    = (const float*)d_in[2];
    const float* wv    = (const float*)d_in[3];
    const float* wo    = (const float*)d_in[4];
    const float* kc_in = (const float*)d_in[5];
    const float* vc_in = (const float*)d_in[6];
    const int* positions = (const int*)d_in[7];
    const int* widx      = (const int*)d_in[8];

    float* out_kc = (float*)d_out;
    float* out_vc = out_kc + (size_t)NSLOTS * NKV * HD;
    float* out_o  = out_vc + (size_t)NSLOTS * NKV * HD;

    const size_t cacheBytes = (size_t)NSLOTS * NKV * HD * sizeof(float);
    cudaMemcpyAsync(out_kc, kc_in, cacheBytes, cudaMemcpyDeviceToDevice, 0);
    cudaMemcpyAsync(out_vc, vc_in, cacheBytes, cudaMemcpyDeviceToDevice, 0);

    k_gemm_qkv<<<dim3(48, TSEQ / 128), 256, 0, 0>>>(x, wq, wk, wv);
    k_rope<<<TSEQ, 256, 0, 0>>>(positions, widx, out_kc, out_vc);

    const int attn_smem = ATTN_SMEM_FLOATS * (int)sizeof(float);
    cudaFuncSetAttribute(k_attn, cudaFuncAttributeMaxDynamicSharedMemorySize,
                         attn_smem);
    k_attn<<<dim3(TSEQ / 64, NQ), 256, attn_smem, 0>>>(positions);

    k_gemm_o<<<dim3(DDIM / 128, TSEQ / 128), 256, 0, 0>>>(wo, out_o);
}

// round 4
// speedup vs baseline: 5.0820x; 1.6123x over previous
#include <cuda_runtime.h>
#include <cstdint>
#include <stdint.h>
#include <math.h>

// Problem constants (fixed by the dataset)
#define TSEQ   2048
#define DDIM   4096
#define NQ     32
#define NKV    8
#define HD     128
#define NSLOTS 32768
#define QKVC   6144   // 32*128 + 8*128 + 8*128

// ---------------- scratch (static device allocations; no cudaMalloc) -------
__device__ float g_QKV[(size_t)TSEQ * QKVC];       // [t][6144]
__device__ float g_Q  [(size_t)NQ  * TSEQ * HD];   // [n][t][h] (roped, scaled)
__device__ float g_K  [(size_t)NKV * TSEQ * HD];   // [kh][t][h] (roped)
__device__ float g_V  [(size_t)NKV * TSEQ * HD];   // [kh][t][h]
__device__ float g_A2 [(size_t)TSEQ * DDIM];       // [t][n*128+h]

// ---------------- tf32 mma helpers -----------------------------------------
__device__ __forceinline__ unsigned f2tf(float x) {
    unsigned r;
    asm("cvt.rna.tf32.f32 %0, %1;" : "=r"(r) : "f"(x));
    return r;
}

__device__ __forceinline__ void mma_tf32(float* d, const unsigned* a,
                                         const unsigned* b) {
    asm volatile(
        "mma.sync.aligned.m16n8k8.row.col.f32.tf32.tf32.f32 "
        "{%0,%1,%2,%3}, {%4,%5,%6,%7}, {%8,%9}, {%0,%1,%2,%3};"
        : "+f"(d[0]), "+f"(d[1]), "+f"(d[2]), "+f"(d[3])
        : "r"(a[0]), "r"(a[1]), "r"(a[2]), "r"(a[3]), "r"(b[0]), "r"(b[1]));
}

__device__ __forceinline__ void cp16(unsigned smem, const float* g) {
    asm volatile("cp.async.cg.shared.global [%0], [%1], 16;\n"
                 :: "r"(smem), "l"(g));
}

// ---------------- 128x128 tf32 tensor-core GEMM tile -----------------------
__device__ __forceinline__ void gemm_mma128(
    const float* __restrict__ A, int lda,
    const float* __restrict__ B, int ldb,
    float* __restrict__ C, int ldc,
    int Kdim, int rowBase)
{
    __shared__ float As[2][128][20];
    __shared__ float Bs[2][16][136];

    const int tid  = threadIdx.x;
    const int lane = tid & 31;
    const int warp = tid >> 5;
    const int wM   = warp >> 2;
    const int wN   = warp & 3;
    const int g    = lane >> 2;
    const int t    = lane & 3;

    const int ar = tid >> 2, ac = (tid & 3) << 2;
    const int br = tid >> 5, bc = (tid & 31) << 2;

    const float* Ab = A + (size_t)rowBase * lda;

    float acc[4][4][4];
#pragma unroll
    for (int mt = 0; mt < 4; mt++)
#pragma unroll
        for (int nt = 0; nt < 4; nt++)
#pragma unroll
            for (int i = 0; i < 4; i++) acc[mt][nt][i] = 0.f;

    const unsigned sA0 = (unsigned)__cvta_generic_to_shared(&As[0][0][0]);
    const unsigned sB0 = (unsigned)__cvta_generic_to_shared(&Bs[0][0][0]);

    {
        cp16(sA0 + (unsigned)((ar)      * 20 + ac) * 4u, Ab + (size_t)ar * lda + ac);
        cp16(sA0 + (unsigned)((ar + 64) * 20 + ac) * 4u, Ab + (size_t)(ar + 64) * lda + ac);
        cp16(sB0 + (unsigned)((br)      * 136 + bc) * 4u, B + (size_t)br * ldb + bc);
        cp16(sB0 + (unsigned)((br + 8)  * 136 + bc) * 4u, B + (size_t)(br + 8) * ldb + bc);
        asm volatile("cp.async.commit_group;");
    }

    const int niter = Kdim >> 4;
    for (int it = 0; it < niter; it++) {
        if (it + 1 < niter) {
            const int k0 = (it + 1) << 4;
            const unsigned stA = sA0 + (unsigned)((it + 1) & 1) * (unsigned)(128 * 20 * 4);
            const unsigned stB = sB0 + (unsigned)((it + 1) & 1) * (unsigned)(16 * 136 * 4);
            cp16(stA + (unsigned)((ar)      * 20 + ac) * 4u, Ab + (size_t)ar * lda + k0 + ac);
            cp16(stA + (unsigned)((ar + 64) * 20 + ac) * 4u, Ab + (size_t)(ar + 64) * lda + k0 + ac);
            cp16(stB + (unsigned)((br)      * 136 + bc) * 4u, B + (size_t)(k0 + br) * ldb + bc);
            cp16(stB + (unsigned)((br + 8)  * 136 + bc) * 4u, B + (size_t)(k0 + br + 8) * ldb + bc);
        }
        asm volatile("cp.async.commit_group;");
        asm volatile("cp.async.wait_group 1;");
        __syncthreads();

        const int st = it & 1;
#pragma unroll
        for (int ks = 0; ks < 2; ks++) {
            unsigned af[4][4], bf[4][2];
#pragma unroll
            for (int mt = 0; mt < 4; mt++) {
                const float* p = &As[st][wM * 64 + mt * 16 + g][ks * 8 + t];
                af[mt][0] = f2tf(p[0]);
                af[mt][1] = f2tf(p[8 * 20]);
                af[mt][2] = f2tf(p[4]);
                af[mt][3] = f2tf(p[8 * 20 + 4]);
            }
#pragma unroll
            for (int nt = 0; nt < 4; nt++) {
                bf[nt][0] = f2tf(Bs[st][ks * 8 + t    ][wN * 32 + nt * 8 + g]);
                bf[nt][1] = f2tf(Bs[st][ks * 8 + t + 4][wN * 32 + nt * 8 + g]);
            }
#pragma unroll
            for (int mt = 0; mt < 4; mt++)
#pragma unroll
                for (int nt = 0; nt < 4; nt++)
                    mma_tf32(acc[mt][nt], af[mt], bf[nt]);
        }
        __syncthreads();
    }

#pragma unroll
    for (int mt = 0; mt < 4; mt++) {
#pragma unroll
        for (int nt = 0; nt < 4; nt++) {
            const int r0 = rowBase + wM * 64 + mt * 16 + g;
            const int c0 = wN * 32 + nt * 8 + 2 * t;
            float2 v0 = {acc[mt][nt][0], acc[mt][nt][1]};
            float2 v1 = {acc[mt][nt][2], acc[mt][nt][3]};
            *(float2*)(C + (size_t)r0 * ldc + c0)       = v0;
            *(float2*)(C + (size_t)(r0 + 8) * ldc + c0) = v1;
        }
    }
}

// ---------------- kernel 1: fused QKV projection ---------------------------
__global__ __launch_bounds__(256) void k_gemm_qkv(
    const float* __restrict__ x,
    const float* __restrict__ wq,
    const float* __restrict__ wk,
    const float* __restrict__ wv)
{
    int cb = blockIdx.x;
    const float* B;
    if (cb < 32)      B = wq + (size_t)cb * DDIM * HD;
    else if (cb < 40) B = wk + (size_t)(cb - 32) * DDIM * HD;
    else              B = wv + (size_t)(cb - 40) * DDIM * HD;
    gemm_mma128(x, DDIM, B, HD, g_QKV + (size_t)cb * HD, QKVC,
                DDIM, blockIdx.y * 128);
}

// ---------------- kernel 2: RoPE + layout split + cache writeback ----------
__global__ __launch_bounds__(256) void k_rope(
    const int* __restrict__ positions,
    const int* __restrict__ widx,
    float* __restrict__ out_kc,
    float* __restrict__ out_vc)
{
    const int t = blockIdx.x;
    __shared__ float cs[64], sn[64];
    const int pos = positions[t];
    if (threadIdx.x < 64) {
        int i = threadIdx.x;
        double e = -((double)(2 * i) / 128.0);
        float inv = (float)pow(500000.0, e);
        float ang = (float)pos * inv;
        float s, c;
        sincosf(ang, &s, &c);
        cs[i] = c;
        sn[i] = s;
    }
    __syncthreads();

    const float* row = g_QKV + (size_t)t * QKVC;
    const int wi = widx[t];
    const float qscale = 0.08838834764831845f;  // 128^-0.5

    for (int idx = threadIdx.x; idx < NQ * 64; idx += blockDim.x) {
        int n = idx >> 6, i = idx & 63;
        float x1 = row[n * HD + i];
        float x2 = row[n * HD + 64 + i];
        float c = cs[i], s = sn[i];
        float* qd = g_Q + ((size_t)n * TSEQ + t) * HD;
        qd[i]      = (x1 * c - x2 * s) * qscale;
        qd[64 + i] = (x2 * c + x1 * s) * qscale;
    }
    for (int idx = threadIdx.x; idx < NKV * 64; idx += blockDim.x) {
        int kh = idx >> 6, i = idx & 63;
        float x1 = row[NQ * HD + kh * HD + i];
        float x2 = row[NQ * HD + kh * HD + 64 + i];
        float c = cs[i], s = sn[i];
        float o1 = x1 * c - x2 * s;
        float o2 = x2 * c + x1 * s;
        float* kd = g_K + ((size_t)kh * TSEQ + t) * HD;
        kd[i] = o1; kd[64 + i] = o2;
        float* kc = out_kc + ((size_t)wi * NKV + kh) * HD;
        kc[i] = o1; kc[64 + i] = o2;
    }
    for (int idx = threadIdx.x; idx < NKV * HD; idx += blockDim.x) {
        int kh = idx >> 7, h = idx & 127;
        float v = row[(NQ + NKV) * HD + kh * HD + h];
        g_V[((size_t)kh * TSEQ + t) * HD + h] = v;
        out_vc[((size_t)wi * NKV + kh) * HD + h] = v;
    }
}

// ---------------- kernel 3: tf32-mma causal flash attention ----------------
// grid = (T/64, NQ), 128 threads (4 warps). Warp w owns query rows w*16..+15.
// Key chunk = 64. Q in fp32 smem (split hi/lo at frag load); K/V pre-converted
// to tf32 bits in smem. P staged through smem (aliases K buffer) as tf32 bits.
//
// smem float-offset layout (dynamic):
//   Qs  [64][132] fp32    @ 0      (8448)
//   Ks  [64][132] tf32    @ 8448   (8448)   <- aliased by Ps [64][68] in PV
//   Vs  [64][132] tf32    @ 16896  (8448)
//   PKs [64] int          @ 25344  (64)
#define ATTN2_SMEM_FLOATS (8448 * 3 + 64)
__global__ __launch_bounds__(128) void k_attn_mma(const int* __restrict__ positions)
{
    extern __shared__ float sm[];
    float*    Qs  = sm;
    unsigned* Ks  = (unsigned*)(sm + 8448);
    unsigned* Vs  = (unsigned*)(sm + 16896);
    int*      PKs = (int*)(sm + 25344);
    unsigned* Ps  = Ks;               // alias (Ks dead once S is computed)

    const int n    = blockIdx.y;
    const int kh   = n >> 2;
    const int t0   = blockIdx.x * 64;
    const int tid  = threadIdx.x;
    const int lane = tid & 31;
    const int w    = tid >> 5;
    const int g    = lane >> 2;       // mma groupID 0..7
    const int t    = lane & 3;        // mma thread-in-group 0..3

    // ---- load Q tile (64x128 fp32) ----
    const float* Qg = g_Q + ((size_t)n * TSEQ + t0) * HD;
    for (int i = tid; i < 2048; i += 128) {
        int r = i >> 5, c = (i & 31) << 2;
        *(float4*)(Qs + r * 132 + c) = *(const float4*)(Qg + (size_t)r * HD + c);
    }

    const int row0 = w * 16 + g;      // local row (and row+8)
    const int pq0 = positions[t0 + row0];
    const int pq1 = positions[t0 + row0 + 8];

    float m0 = -1e30f, m1 = -1e30f, l0 = 0.f, l1 = 0.f;
    float o[16][4];
#pragma unroll
    for (int nt = 0; nt < 16; nt++)
#pragma unroll
        for (int i = 0; i < 4; i++) o[nt][i] = 0.f;

    const float* Kg = g_K + (size_t)kh * TSEQ * HD;
    const float* Vg = g_V + (size_t)kh * TSEQ * HD;

    const int nchunks = blockIdx.x + 1;
    for (int ch = 0; ch < nchunks; ch++) {
        const int s0 = ch * 64;
        __syncthreads();              // prev chunk's Ps/Vs reads done (also Q on ch=0)

        // ---- load K/V chunk, convert to tf32 bits ----
        for (int i = tid; i < 2048; i += 128) {
            int r = i >> 5, c = (i & 31) << 2;
            float4 kv = *(const float4*)(Kg + (size_t)(s0 + r) * HD + c);
            uint4 kb = {f2tf(kv.x), f2tf(kv.y), f2tf(kv.z), f2tf(kv.w)};
            *(uint4*)(Ks + r * 132 + c) = kb;
            float4 vv = *(const float4*)(Vg + (size_t)(s0 + r) * HD + c);
            uint4 vb = {f2tf(vv.x), f2tf(vv.y), f2tf(vv.z), f2tf(vv.w)};
            *(uint4*)(Vs + r * 132 + c) = vb;
        }
        if (tid < 64) PKs[tid] = positions[s0 + tid];
        __syncthreads();

        // ---- S = Q K^T (64x64), split-Q compensated ----
        float s[8][4];
#pragma unroll
        for (int nt = 0; nt < 8; nt++)
#pragma unroll
            for (int i = 0; i < 4; i++) s[nt][i] = 0.f;

#pragma unroll
        for (int ks = 0; ks < 16; ks++) {
            const int k0 = ks * 8;
            const float* qp = Qs + row0 * 132 + k0;
            float f0 = qp[t], f1 = qp[8 * 132 + t];
            float f2 = qp[t + 4], f3 = qp[8 * 132 + t + 4];
            unsigned ah[4], al[4];
            ah[0] = f2tf(f0); al[0] = f2tf(f0 - __uint_as_float(ah[0]));
            ah[1] = f2tf(f1); al[1] = f2tf(f1 - __uint_as_float(ah[1]));
            ah[2] = f2tf(f2); al[2] = f2tf(f2 - __uint_as_float(ah[2]));
            ah[3] = f2tf(f3); al[3] = f2tf(f3 - __uint_as_float(ah[3]));
#pragma unroll
            for (int nt = 0; nt < 8; nt++) {
                const unsigned* kp = Ks + (nt * 8 + g) * 132 + k0;
                unsigned bb[2] = {kp[t], kp[t + 4]};
                mma_tf32(s[nt], ah, bb);
                mma_tf32(s[nt], al, bb);
            }
        }

        // ---- mask + online softmax ----
        float mx0 = -1e30f, mx1 = -1e30f;
#pragma unroll
        for (int nt = 0; nt < 8; nt++) {
            const int col = nt * 8 + 2 * t;
            int2 pk = *(const int2*)(PKs + col);
            if (pq0 < pk.x) s[nt][0] = -1e30f;
            if (pq0 < pk.y) s[nt][1] = -1e30f;
            if (pq1 < pk.x) s[nt][2] = -1e30f;
            if (pq1 < pk.y) s[nt][3] = -1e30f;
            mx0 = fmaxf(mx0, fmaxf(s[nt][0], s[nt][1]));
            mx1 = fmaxf(mx1, fmaxf(s[nt][2], s[nt][3]));
        }
        mx0 = fmaxf(mx0, __shfl_xor_sync(0xffffffffu, mx0, 1));
        mx0 = fmaxf(mx0, __shfl_xor_sync(0xffffffffu, mx0, 2));
        mx1 = fmaxf(mx1, __shfl_xor_sync(0xffffffffu, mx1, 1));
        mx1 = fmaxf(mx1, __shfl_xor_sync(0xffffffffu, mx1, 2));

        const float mn0 = fmaxf(m0, mx0), mn1 = fmaxf(m1, mx1);
        const float c0 = __expf(m0 - mn0), c1 = __expf(m1 - mn1);
        m0 = mn0; m1 = mn1;

        float sum0 = 0.f, sum1 = 0.f;
#pragma unroll
        for (int nt = 0; nt < 8; nt++) {
            s[nt][0] = __expf(s[nt][0] - mn0);
            s[nt][1] = __expf(s[nt][1] - mn0);
            s[nt][2] = __expf(s[nt][2] - mn1);
            s[nt][3] = __expf(s[nt][3] - mn1);
            sum0 += s[nt][0] + s[nt][1];
            sum1 += s[nt][2] + s[nt][3];
        }
        sum0 += __shfl_xor_sync(0xffffffffu, sum0, 1);
        sum0 += __shfl_xor_sync(0xffffffffu, sum0, 2);
        sum1 += __shfl_xor_sync(0xffffffffu, sum1, 1);
        sum1 += __shfl_xor_sync(0xffffffffu, sum1, 2);
        l0 = l0 * c0 + sum0;
        l1 = l1 * c1 + sum1;

#pragma unroll
        for (int nt = 0; nt < 16; nt++) {
            o[nt][0] *= c0; o[nt][1] *= c0;
            o[nt][2] *= c1; o[nt][3] *= c1;
        }

        __syncthreads();              // all warps done reading Ks before Ps overwrite

        // ---- stage P (tf32 bits) into smem; each warp writes only its rows ----
#pragma unroll
        for (int nt = 0; nt < 8; nt++) {
            const int col = nt * 8 + 2 * t;
            uint2 p01 = {f2tf(s[nt][0]), f2tf(s[nt][1])};
            uint2 p23 = {f2tf(s[nt][2]), f2tf(s[nt][3])};
            *(uint2*)(Ps + row0 * 68 + col)       = p01;
            *(uint2*)(Ps + (row0 + 8) * 68 + col) = p23;
        }
        __syncwarp();

        // ---- O += P V (each warp reads only its own P rows) ----
#pragma unroll
        for (int ks = 0; ks < 8; ks++) {
            const int k0 = ks * 8;
            const unsigned* pp = Ps + row0 * 68 + k0;
            unsigned a[4] = {pp[t], pp[8 * 68 + t], pp[t + 4], pp[8 * 68 + t + 4]};
#pragma unroll
            for (int nt = 0; nt < 16; nt++) {
                const unsigned* vp = Vs + (k0 + t) * 132 + nt * 8 + g;
                unsigned bb[2] = {vp[0], vp[4 * 132]};
                mma_tf32(o[nt], a, bb);
            }
        }
    }

    // ---- epilogue ----
    const float inv0 = 1.f / l0, inv1 = 1.f / l1;
    float* outr0 = g_A2 + (size_t)(t0 + row0) * DDIM + n * HD;
    float* outr1 = g_A2 + (size_t)(t0 + row0 + 8) * DDIM + n * HD;
#pragma unroll
    for (int nt = 0; nt < 16; nt++) {
        const int col = nt * 8 + 2 * t;
        float2 v0 = {o[nt][0] * inv0, o[nt][1] * inv0};
        float2 v1 = {o[nt][2] * inv1, o[nt][3] * inv1};
        *(float2*)(outr0 + col) = v0;
        *(float2*)(outr1 + col) = v1;
    }
}

// ---------------- kernel 4: output projection ------------------------------
__global__ __launch_bounds__(256) void k_gemm_o(
    const float* __restrict__ wo, float* __restrict__ out_o)
{
    gemm_mma128(g_A2, DDIM, wo + (size_t)blockIdx.x * 128, DDIM,
                out_o + (size_t)blockIdx.x * 128, DDIM,
                DDIM, blockIdx.y * 128);
}

// ---------------- launch ----------------------------------------------------
extern "C" void kernel_launch(void* const* d_in, const int* in_sizes, int n_in,
                              void* d_out, int out_size)
{
    (void)in_sizes; (void)n_in; (void)out_size;
    const float* x     = (const float*)d_in[0];
    const float* wq    = (const float*)d_in[1];
    const float* wk    = (const float*)d_in[2];
    const float* wv    = (const float*)d_in[3];
    const float* wo    = (const float*)d_in[4];
    const float* kc_in = (const float*)d_in[5];
    const float* vc_in = (const float*)d_in[6];
    const int* positions = (const int*)d_in[7];
    const int* widx      = (const int*)d_in[8];

    float* out_kc = (float*)d_out;
    float* out_vc = out_kc + (size_t)NSLOTS * NKV * HD;
    float* out_o  = out_vc + (size_t)NSLOTS * NKV * HD;

    const size_t cacheBytes = (size_t)NSLOTS * NKV * HD * sizeof(float);
    cudaMemcpyAsync(out_kc, kc_in, cacheBytes, cudaMemcpyDeviceToDevice, 0);
    cudaMemcpyAsync(out_vc, vc_in, cacheBytes, cudaMemcpyDeviceToDevice, 0);

    k_gemm_qkv<<<dim3(48, TSEQ / 128), 256, 0, 0>>>(x, wq, wk, wv);
    k_rope<<<TSEQ, 256, 0, 0>>>(positions, widx, out_kc, out_vc);

    const int attn_smem = ATTN2_SMEM_FLOATS * (int)sizeof(float);
    cudaFuncSetAttribute(k_attn_mma,
                         cudaFuncAttributeMaxDynamicSharedMemorySize, attn_smem);
    k_attn_mma<<<dim3(TSEQ / 64, NQ), 128, attn_smem, 0>>>(positions);

    k_gemm_o<<<dim3(DDIM / 128, TSEQ / 128), 256, 0, 0>>>(wo, out_o);
}